// round 4
// baseline (speedup 1.0000x reference)
#include <cuda_runtime.h>
#include <cstdint>
#include <cstddef>

// ---------------- problem constants ----------------
#define D_MODEL  1024
#define D_STATE  16
#define D_INNER  2048
#define DT_RANK  64
#define BATCH    2
#define SEQ      2048
#define NROWS    (BATCH * SEQ)           // 4096
#define DBC_COLS 96

// ---------------- scratch (static device globals; no allocation) ----------------
__device__ float g_xr [(size_t)NROWS * (2 * D_INNER)];
__device__ float g_u  [(size_t)NROWS * D_INNER];
__device__ float g_dbc[(size_t)NROWS * DBC_COLS];
__device__ float g_dt [(size_t)NROWS * D_INNER];
__device__ float g_y  [(size_t)NROWS * D_INNER];
__device__ float g_wt [(size_t)4096 * 1024];     // transposed weights [N,K], tf32-rounded

// ---------------- helpers ----------------
__device__ __forceinline__ float silu_f(float x) { return x / (1.0f + __expf(-x)); }
__device__ __forceinline__ float softplus_f(float x) { return (x > 20.0f) ? x : log1pf(__expf(x)); }
__device__ __forceinline__ unsigned tf32_of(float x) {
    unsigned r; asm("cvt.rna.tf32.f32 %0, %1;" : "=r"(r) : "f"(x)); return r;
}
__device__ __forceinline__ void mma_tf32(float* d, const uint4& a, const uint2& b) {
    asm volatile(
        "mma.sync.aligned.m16n8k8.row.col.f32.tf32.tf32.f32 "
        "{%0,%1,%2,%3}, {%4,%5,%6,%7}, {%8,%9}, {%0,%1,%2,%3};"
        : "+f"(d[0]), "+f"(d[1]), "+f"(d[2]), "+f"(d[3])
        : "r"(a.x), "r"(a.y), "r"(a.z), "r"(a.w), "r"(b.x), "r"(b.y));
}

// ---------------- fragment-major tf32 tensor-core GEMM ----------------
// C[M, N_total] = A[M, K] (row-major, lda) @ Wt[N, K]^T   (Wt row-major, pre-tf32)
// Block tile 128x128, BK=16, 8 warps: warp tile 64x32 (2 M-warps x 4 N-warps).
// Shared layout is fragment-major: each m16k8 A-fragment stored as 32 lanes x 16B,
// each n8k8 B-fragment as 32 lanes x 8B -> compute loop = LDS.128/LDS.64 only.
// mode 0: plain store. mode 1: softplus(acc + bias[col]).
__global__ __launch_bounds__(256, 2) void gemm_frag(
    const float* __restrict__ A, int lda,
    const float* __restrict__ Wt,
    const float* __restrict__ bias,
    float* __restrict__ C, int N_total, int K, int mode)
{
    // [buf][slab(2)][block][lane][reg]
    __shared__ float As[2][2][8][32][4];   // 16 KB
    __shared__ float Bs[2][2][16][32][2];  // 16 KB

    const int tid  = threadIdx.x;
    const int w    = tid >> 5;
    const int l    = tid & 31;
    const int mm   = l >> 2;   // group id 0..7
    const int kk   = l & 3;    // thread-in-group 0..3
    const int mBase = blockIdx.y * 128;
    const int nBase = blockIdx.x * 128;

    // loader roles
    const int sA  = w & 1;         // slab handled by this warp (A and B)
    const int iA0 = w >> 1;        // A blocks iA0, iA0+4
    const int jB0 = w >> 1;        // B blocks jB0, jB0+4, jB0+8, jB0+12

    float acc[4][4][4];
#pragma unroll
    for (int i = 0; i < 4; i++)
#pragma unroll
        for (int j = 0; j < 4; j++)
#pragma unroll
            for (int q = 0; q < 4; q++) acc[i][j][q] = 0.0f;

    float ra[2][4];   // A staging: 2 lane-slots x 4 regs
    float rb[4][2];   // B staging: 4 lane-slots x 2 regs

    auto ldg = [&](int k0) {
#pragma unroll
        for (int q = 0; q < 2; q++) {
            const float* ap = A + (size_t)(mBase + (iA0 + 4 * q) * 16 + mm) * lda
                                + (k0 + sA * 8 + kk);
#pragma unroll
            for (int r = 0; r < 4; r++)
                ra[q][r] = ap[(size_t)(r & 1) * 8 * lda + (r >> 1) * 4];
        }
#pragma unroll
        for (int q = 0; q < 4; q++) {
            int n = nBase + (jB0 + 4 * q) * 8 + mm;
            if (n < N_total) {
                const float* bp = Wt + (size_t)n * K + (k0 + sA * 8 + kk);
                rb[q][0] = bp[0];
                rb[q][1] = bp[4];
            } else {
                rb[q][0] = 0.0f; rb[q][1] = 0.0f;
            }
        }
    };
    auto sts = [&](int buf) {
#pragma unroll
        for (int q = 0; q < 2; q++) {
            float4 v;
            v.x = __uint_as_float(tf32_of(ra[q][0]));
            v.y = __uint_as_float(tf32_of(ra[q][1]));
            v.z = __uint_as_float(tf32_of(ra[q][2]));
            v.w = __uint_as_float(tf32_of(ra[q][3]));
            *reinterpret_cast<float4*>(&As[buf][sA][iA0 + 4 * q][l][0]) = v;
        }
#pragma unroll
        for (int q = 0; q < 4; q++) {
            float2 v; v.x = rb[q][0]; v.y = rb[q][1];
            *reinterpret_cast<float2*>(&Bs[buf][sA][jB0 + 4 * q][l][0]) = v;
        }
    };

    const int wmB = (w & 1) * 4;   // warp's A block origin (m)
    const int wnB = (w >> 1) * 4;  // warp's B block origin (n)

    auto compute = [&](int buf) {
#pragma unroll
        for (int s = 0; s < 2; s++) {
            uint4 af[4];
            uint2 bf[4];
#pragma unroll
            for (int i = 0; i < 4; i++)
                af[i] = *reinterpret_cast<const uint4*>(&As[buf][s][wmB + i][l][0]);
#pragma unroll
            for (int j = 0; j < 4; j++)
                bf[j] = *reinterpret_cast<const uint2*>(&Bs[buf][s][wnB + j][l][0]);
#pragma unroll
            for (int i = 0; i < 4; i++)
#pragma unroll
                for (int j = 0; j < 4; j++)
                    mma_tf32(acc[i][j], af[i], bf[j]);
        }
    };

    // prologue
    ldg(0); sts(0);
    __syncthreads();

    const int nt = K / 16;
    for (int t = 0; t < nt; t++) {
        const int buf = t & 1;
        const bool more = (t + 1 < nt);
        if (more) ldg((t + 1) * 16);
        compute(buf);
        if (more) sts(buf ^ 1);
        __syncthreads();
    }

    // epilogue (c0,c1 at row gid / cols tig*2..+1; c2,c3 at row gid+8)
#pragma unroll
    for (int i = 0; i < 4; i++) {
        int r0 = mBase + (w & 1) * 64 + i * 16 + mm;
#pragma unroll
        for (int j = 0; j < 4; j++) {
            int cc = nBase + (w >> 1) * 32 + j * 8 + kk * 2;
            if (cc < N_total) {
                float2 v0, v1;
                v0.x = acc[i][j][0]; v0.y = acc[i][j][1];
                v1.x = acc[i][j][2]; v1.y = acc[i][j][3];
                if (mode == 1) {
                    float b0 = bias[cc], b1 = bias[cc + 1];
                    v0.x = softplus_f(v0.x + b0); v0.y = softplus_f(v0.y + b1);
                    v1.x = softplus_f(v1.x + b0); v1.y = softplus_f(v1.y + b1);
                }
                *reinterpret_cast<float2*>(C + (size_t)r0 * N_total + cc)       = v0;
                *reinterpret_cast<float2*>(C + (size_t)(r0 + 8) * N_total + cc) = v1;
            }
        }
    }
}

// ---------------- weight transpose with tf32 rounding: out[n][k] = tf32(in[k][n]) ----------------
__global__ void transpose_cvt(const float* __restrict__ in, float* __restrict__ out, int K, int N)
{
    __shared__ float t[32][33];
    const int n0 = blockIdx.x * 32, k0 = blockIdx.y * 32;
    for (int r = threadIdx.y; r < 32; r += 8)
        t[r][threadIdx.x] = in[(size_t)(k0 + r) * N + n0 + threadIdx.x];
    __syncthreads();
    for (int r = threadIdx.y; r < 32; r += 8)
        out[(size_t)(n0 + r) * K + k0 + threadIdx.x] =
            __uint_as_float(tf32_of(t[threadIdx.x][r]));
}

// ---------------- causal depthwise conv1d + silu ----------------
__global__ void conv_silu_k(const float* __restrict__ conv_w,
                            const float* __restrict__ conv_b)
{
    size_t idx = (size_t)blockIdx.x * blockDim.x + threadIdx.x;
    if (idx >= (size_t)NROWS * D_INNER) return;
    int d = (int)(idx % D_INNER);
    int l = (int)((idx / D_INNER) % SEQ);
    int b = (int)(idx / ((size_t)D_INNER * SEQ));

    float acc = conv_b[d];
    const float w0 = conv_w[d * 4 + 0];
    const float w1 = conv_w[d * 4 + 1];
    const float w2 = conv_w[d * 4 + 2];
    const float w3 = conv_w[d * 4 + 3];
    const size_t base = ((size_t)b * SEQ) * (2 * D_INNER) + d;
    const size_t rs = 2 * D_INNER;
    if (l - 3 >= 0) acc = fmaf(g_xr[base + (size_t)(l - 3) * rs], w0, acc);
    if (l - 2 >= 0) acc = fmaf(g_xr[base + (size_t)(l - 2) * rs], w1, acc);
    if (l - 1 >= 0) acc = fmaf(g_xr[base + (size_t)(l - 1) * rs], w2, acc);
    acc = fmaf(g_xr[base + (size_t)l * rs], w3, acc);

    g_u[((size_t)b * SEQ + l) * D_INNER + d] = silu_f(acc);
}

// ---------------- selective scan (smem-chunked, double-buffered) ----------------
#define TCH 32
__global__ __launch_bounds__(256) void scan_k(
    const float* __restrict__ A_log,
    const float* __restrict__ Dv)
{
    __shared__ float s_dt [2][TCH][16];
    __shared__ float s_u  [2][TCH][16];
    __shared__ float s_res[2][TCH][16];
    __shared__ float s_bc [2][TCH][32];
    __shared__ float s_y  [TCH][16];

    const int b    = blockIdx.y;
    const int d0   = blockIdx.x * 16;
    const int tid  = threadIdx.x;
    const int dloc = tid >> 4;
    const int n    = tid & 15;
    const int d    = d0 + dloc;

    const float Acoef = -__expf(A_log[d * D_STATE + n]);
    const float Dd    = Dv[d];
    float h = 0.0f;
    const size_t rowBase = (size_t)b * SEQ;

    auto load_chunk = [&](int l0, int buf) {
#pragma unroll
        for (int p = 0; p < 2; p++) {
            int e = p * 256 + tid, row = e >> 4, col = e & 15;
            size_t gRow = rowBase + l0 + row;
            s_dt [buf][row][col] = g_dt[gRow * D_INNER + d0 + col];
            s_u  [buf][row][col] = g_u [gRow * D_INNER + d0 + col];
            s_res[buf][row][col] = g_xr[gRow * (2 * D_INNER) + D_INNER + d0 + col];
        }
#pragma unroll
        for (int p = 0; p < 4; p++) {
            int e = p * 256 + tid, row = e >> 5, col = e & 31;
            s_bc[buf][row][col] =
                g_dbc[(rowBase + l0 + row) * DBC_COLS + DT_RANK + col];
        }
    };

    load_chunk(0, 0);
    __syncthreads();

    const int NCH = SEQ / TCH;
    for (int c = 0; c < NCH; c++) {
        const int buf = c & 1;
        if (c + 1 < NCH) load_chunk((c + 1) * TCH, buf ^ 1);

#pragma unroll 8
        for (int t = 0; t < TCH; t++) {
            float dt = s_dt[buf][t][dloc];
            float u  = s_u [buf][t][dloc];
            float Bn = s_bc[buf][t][n];
            float Cn = s_bc[buf][t][16 + n];
            float dA = __expf(dt * Acoef);
            h = fmaf(h, dA, (dt * u) * Bn);
            float v = h * Cn;
            v += __shfl_xor_sync(0xffffffffu, v, 8);
            v += __shfl_xor_sync(0xffffffffu, v, 4);
            v += __shfl_xor_sync(0xffffffffu, v, 2);
            v += __shfl_xor_sync(0xffffffffu, v, 1);
            if (n == 0) s_y[t][dloc] = fmaf(Dd, u, v);
        }
        __syncthreads();

#pragma unroll
        for (int p = 0; p < 2; p++) {
            int e = p * 256 + tid, row = e >> 4, col = e & 15;
            float r = s_res[buf][row][col];
            g_y[(rowBase + c * TCH + row) * D_INNER + d0 + col] =
                s_y[row][col] * silu_f(r);
        }
        __syncthreads();
    }
}

// ---------------- launch ----------------
extern "C" void kernel_launch(void* const* d_in, const int* in_sizes, int n_in,
                              void* d_out, int out_size)
{
    const float* x          = (const float*)d_in[0];
    const float* in_proj_w  = (const float*)d_in[1];
    const float* conv_w     = (const float*)d_in[2];
    const float* conv_b     = (const float*)d_in[3];
    const float* x_proj_w   = (const float*)d_in[4];
    const float* dt_proj_w  = (const float*)d_in[5];
    const float* dt_proj_b  = (const float*)d_in[6];
    const float* A_log      = (const float*)d_in[7];
    const float* Dv         = (const float*)d_in[8];
    const float* out_proj_w = (const float*)d_in[9];
    float* out = (float*)d_out;

    float* xr  = nullptr; cudaGetSymbolAddress((void**)&xr,  g_xr);
    float* u   = nullptr; cudaGetSymbolAddress((void**)&u,   g_u);
    float* dbc = nullptr; cudaGetSymbolAddress((void**)&dbc, g_dbc);
    float* dt  = nullptr; cudaGetSymbolAddress((void**)&dt,  g_dt);
    float* y   = nullptr; cudaGetSymbolAddress((void**)&y,   g_y);
    float* wt  = nullptr; cudaGetSymbolAddress((void**)&wt,  g_wt);

    dim3 tb(32, 8);

    // 1) in_proj: Wt = tf32(in_proj_w)^T [4096,1024]; xr = x @ W  (4096x4096, K=1024)
    transpose_cvt<<<dim3(4096 / 32, 1024 / 32), tb>>>(in_proj_w, wt, 1024, 4096);
    gemm_frag<<<dim3(4096 / 128, NROWS / 128), 256>>>(
        x, D_MODEL, wt, nullptr, xr, 2 * D_INNER, D_MODEL, 0);

    // 2) conv + silu
    {
        size_t total = (size_t)NROWS * D_INNER;
        conv_silu_k<<<(unsigned)((total + 255) / 256), 256>>>(conv_w, conv_b);
    }

    // 3) dbc = u @ x_proj_w  (4096x96, K=2048)
    transpose_cvt<<<dim3(96 / 32, 2048 / 32), tb>>>(x_proj_w, wt, 2048, 96);
    gemm_frag<<<dim3(1, NROWS / 128), 256>>>(
        u, D_INNER, wt, nullptr, dbc, DBC_COLS, D_INNER, 0);

    // 4) dt = softplus(dbc[:, :64] @ dt_proj_w + b)  (4096x2048, K=64)
    transpose_cvt<<<dim3(2048 / 32, 64 / 32), tb>>>(dt_proj_w, wt, 64, 2048);
    gemm_frag<<<dim3(2048 / 128, NROWS / 128), 256>>>(
        dbc, DBC_COLS, wt, dt_proj_b, dt, D_INNER, DT_RANK, 1);

    // 5) selective scan + gating -> y
    scan_k<<<dim3(D_INNER / 16, BATCH), 256>>>(A_log, Dv);

    // 6) out = y @ out_proj_w  (4096x1024, K=2048)
    transpose_cvt<<<dim3(1024 / 32, 2048 / 32), tb>>>(out_proj_w, wt, 2048, 1024);
    gemm_frag<<<dim3(1024 / 128, NROWS / 128), 256>>>(
        y, D_INNER, wt, nullptr, out, D_MODEL, D_INNER, 0);
}

// round 6
// speedup vs baseline: 1.1781x; 1.1781x over previous
#include <cuda_runtime.h>
#include <cstdint>
#include <cstddef>

// ---------------- problem constants ----------------
#define D_MODEL  1024
#define D_STATE  16
#define D_INNER  2048
#define DT_RANK  64
#define BATCH    2
#define SEQ      2048
#define NROWS    (BATCH * SEQ)           // 4096
#define DBC_COLS 96

// ---------------- scratch (static device globals; no allocation) ----------------
__device__ float g_xr [(size_t)NROWS * (2 * D_INNER)];
__device__ float g_u  [(size_t)NROWS * D_INNER];
__device__ float g_dbc[(size_t)NROWS * DBC_COLS];
__device__ float g_dt [(size_t)NROWS * D_INNER];
__device__ float g_y  [(size_t)NROWS * D_INNER];
__device__ float g_wt [(size_t)4096 * 1024];     // transposed weights [N,K], tf32-rounded

// ---------------- helpers ----------------
__device__ __forceinline__ float silu_f(float x) { return x / (1.0f + __expf(-x)); }
__device__ __forceinline__ float softplus_f(float x) { return (x > 20.0f) ? x : log1pf(__expf(x)); }
__device__ __forceinline__ unsigned tf32_of(float x) {
    unsigned r; asm("cvt.rna.tf32.f32 %0, %1;" : "=r"(r) : "f"(x)); return r;
}
__device__ __forceinline__ uint32_t smem_u32(const void* p) {
    uint32_t a;
    asm("{ .reg .u64 t; cvta.to.shared.u64 t, %1; cvt.u32.u64 %0, t; }" : "=r"(a) : "l"(p));
    return a;
}
__device__ __forceinline__ void mma_tf32(float* d, const uint32_t* a, const uint32_t* b) {
    asm volatile(
        "mma.sync.aligned.m16n8k8.row.col.f32.tf32.tf32.f32 "
        "{%0,%1,%2,%3}, {%4,%5,%6,%7}, {%8,%9}, {%0,%1,%2,%3};"
        : "+f"(d[0]), "+f"(d[1]), "+f"(d[2]), "+f"(d[3])
        : "r"(a[0]), "r"(a[1]), "r"(a[2]), "r"(a[3]), "r"(b[0]), "r"(b[1]));
}
__device__ __forceinline__ void ldsm4(uint32_t& r0, uint32_t& r1, uint32_t& r2, uint32_t& r3,
                                      uint32_t addr) {
    asm volatile("ldmatrix.sync.aligned.m8n8.x4.shared.b16 {%0,%1,%2,%3}, [%4];"
                 : "=r"(r0), "=r"(r1), "=r"(r2), "=r"(r3) : "r"(addr));
}

// ---------------- tf32 tensor-core GEMM (ldmatrix feed) ----------------
// C[M, N_total] = A[M, K] (row-major, lda, fp32) @ Wt[N, K]^T (row-major, pre-tf32)
// Block 128x128, BK=16, 8 warps (2 M x 4 N), warp tile 64x32.
// Smem tiles row-major with 20-float row stride (ldmatrix-conflict-free).
// mode 0: plain store; mode 1: softplus(acc + bias[col]).
#define RS 20    // smem row stride in floats
__global__ __launch_bounds__(256, 2) void gemm_ldsm(
    const float* __restrict__ A, int lda,
    const float* __restrict__ Wt,
    const float* __restrict__ bias,
    float* __restrict__ C, int N_total, int K, int mode)
{
    __shared__ float As[2][128][RS];   // 20 KB
    __shared__ float Bs[2][128][RS];   // 20 KB

    const int tid  = threadIdx.x;
    const int w    = tid >> 5;
    const int l    = tid & 31;
    const int mBase = blockIdx.y * 128;
    const int nBase = blockIdx.x * 128;
    const int wmB  = (w & 1) * 64;     // warp m origin
    const int wnB  = (w >> 1) * 32;    // warp n origin

    // ---- loader map: thread t -> row t>>1, two float4 quads {t&1, (t&1)+2} ----
    const int ldRow = tid >> 1;
    const int ldQ0  = (tid & 1);

    // ---- ldmatrix lane address components ----
    const int aRowOff = (l & 7) + ((l >> 3) & 1) * 8;
    const int aColOff = ((l >> 4) & 1) * 4;
    const int bRowOff = (l & 7) + ((l >> 4) & 1) * 8;
    const int bColOff = ((l >> 3) & 1) * 4;

    const uint32_t sAs = smem_u32(&As[0][0][0]);
    const uint32_t sBs = smem_u32(&Bs[0][0][0]);

    float acc[4][4][4];
#pragma unroll
    for (int i = 0; i < 4; i++)
#pragma unroll
        for (int j = 0; j < 4; j++)
#pragma unroll
            for (int q = 0; q < 4; q++) acc[i][j][q] = 0.0f;

    float4 ra[2], rb[2];

    auto ldg = [&](int k0) {
#pragma unroll
        for (int v = 0; v < 2; v++) {
            ra[v] = *reinterpret_cast<const float4*>(
                A + (size_t)(mBase + ldRow) * lda + k0 + (ldQ0 + 2 * v) * 4);
        }
        int n = nBase + ldRow;
        if (n < N_total) {
#pragma unroll
            for (int v = 0; v < 2; v++)
                rb[v] = *reinterpret_cast<const float4*>(
                    Wt + (size_t)n * K + k0 + (ldQ0 + 2 * v) * 4);
        } else {
            rb[0] = make_float4(0.f, 0.f, 0.f, 0.f);
            rb[1] = rb[0];
        }
    };
    auto sts = [&](int buf) {
#pragma unroll
        for (int v = 0; v < 2; v++) {
            float4 t;
            t.x = __uint_as_float(tf32_of(ra[v].x));
            t.y = __uint_as_float(tf32_of(ra[v].y));
            t.z = __uint_as_float(tf32_of(ra[v].z));
            t.w = __uint_as_float(tf32_of(ra[v].w));
            *reinterpret_cast<float4*>(&As[buf][ldRow][(ldQ0 + 2 * v) * 4]) = t;
            *reinterpret_cast<float4*>(&Bs[buf][ldRow][(ldQ0 + 2 * v) * 4]) = rb[v];
        }
    };

    auto compute = [&](int buf) {
        const uint32_t aB = sAs + (uint32_t)(((buf * 128 + wmB + aRowOff) * RS + aColOff) * 4);
        const uint32_t bB = sBs + (uint32_t)(((buf * 128 + wnB + bRowOff) * RS + bColOff) * 4);
#pragma unroll
        for (int s = 0; s < 2; s++) {
            uint32_t af[4][4], bf[4][2];
#pragma unroll
            for (int i = 0; i < 4; i++)
                ldsm4(af[i][0], af[i][1], af[i][2], af[i][3],
                      aB + (uint32_t)((i * 16 * RS + s * 8) * 4));
#pragma unroll
            for (int jj = 0; jj < 2; jj++)
                ldsm4(bf[2 * jj][0], bf[2 * jj][1], bf[2 * jj + 1][0], bf[2 * jj + 1][1],
                      bB + (uint32_t)((jj * 16 * RS + s * 8) * 4));
#pragma unroll
            for (int i = 0; i < 4; i++)
#pragma unroll
                for (int j = 0; j < 4; j++)
                    mma_tf32(acc[i][j], af[i], bf[j]);
        }
    };

    // prologue
    ldg(0); sts(0);
    __syncthreads();

    const int nt = K / 16;
    for (int t = 0; t < nt; t++) {
        const int buf = t & 1;
        const bool more = (t + 1 < nt);
        if (more) ldg((t + 1) * 16);
        compute(buf);
        if (more) sts(buf ^ 1);
        __syncthreads();
    }

    // epilogue
#pragma unroll
    for (int i = 0; i < 4; i++) {
        int r0 = mBase + wmB + i * 16 + (l >> 2);
#pragma unroll
        for (int j = 0; j < 4; j++) {
            int cc = nBase + wnB + j * 8 + (l & 3) * 2;
            if (cc < N_total) {
                float2 v0, v1;
                v0.x = acc[i][j][0]; v0.y = acc[i][j][1];
                v1.x = acc[i][j][2]; v1.y = acc[i][j][3];
                if (mode == 1) {
                    float b0 = bias[cc], b1 = bias[cc + 1];
                    v0.x = softplus_f(v0.x + b0); v0.y = softplus_f(v0.y + b1);
                    v1.x = softplus_f(v1.x + b0); v1.y = softplus_f(v1.y + b1);
                }
                *reinterpret_cast<float2*>(C + (size_t)r0 * N_total + cc)       = v0;
                *reinterpret_cast<float2*>(C + (size_t)(r0 + 8) * N_total + cc) = v1;
            }
        }
    }
}

// ---------------- weight transpose with tf32 rounding: out[n][k] = tf32(in[k][n]) ----------------
__global__ void transpose_cvt(const float* __restrict__ in, float* __restrict__ out, int K, int N)
{
    __shared__ float t[32][33];
    const int n0 = blockIdx.x * 32, k0 = blockIdx.y * 32;
    for (int r = threadIdx.y; r < 32; r += 8)
        t[r][threadIdx.x] = in[(size_t)(k0 + r) * N + n0 + threadIdx.x];
    __syncthreads();
    for (int r = threadIdx.y; r < 32; r += 8)
        out[(size_t)(n0 + r) * K + k0 + threadIdx.x] =
            __uint_as_float(tf32_of(t[threadIdx.x][r]));
}

// ---------------- causal depthwise conv1d + silu ----------------
__global__ void conv_silu_k(const float* __restrict__ conv_w,
                            const float* __restrict__ conv_b)
{
    size_t idx = (size_t)blockIdx.x * blockDim.x + threadIdx.x;
    if (idx >= (size_t)NROWS * D_INNER) return;
    int d = (int)(idx % D_INNER);
    int l = (int)((idx / D_INNER) % SEQ);
    int b = (int)(idx / ((size_t)D_INNER * SEQ));

    float acc = conv_b[d];
    const float w0 = conv_w[d * 4 + 0];
    const float w1 = conv_w[d * 4 + 1];
    const float w2 = conv_w[d * 4 + 2];
    const float w3 = conv_w[d * 4 + 3];
    const size_t base = ((size_t)b * SEQ) * (2 * D_INNER) + d;
    const size_t rs = 2 * D_INNER;
    if (l - 3 >= 0) acc = fmaf(g_xr[base + (size_t)(l - 3) * rs], w0, acc);
    if (l - 2 >= 0) acc = fmaf(g_xr[base + (size_t)(l - 2) * rs], w1, acc);
    if (l - 1 >= 0) acc = fmaf(g_xr[base + (size_t)(l - 1) * rs], w2, acc);
    acc = fmaf(g_xr[base + (size_t)l * rs], w3, acc);

    g_u[((size_t)b * SEQ + l) * D_INNER + d] = silu_f(acc);
}

// ---------------- selective scan (smem-chunked, double-buffered) ----------------
#define TCH 32
__global__ __launch_bounds__(256) void scan_k(
    const float* __restrict__ A_log,
    const float* __restrict__ Dv)
{
    __shared__ float s_dt [2][TCH][16];
    __shared__ float s_u  [2][TCH][16];
    __shared__ float s_res[2][TCH][16];
    __shared__ float s_bc [2][TCH][32];
    __shared__ float s_y  [TCH][16];

    const int b    = blockIdx.y;
    const int d0   = blockIdx.x * 16;
    const int tid  = threadIdx.x;
    const int dloc = tid >> 4;
    const int n    = tid & 15;
    const int d    = d0 + dloc;

    const float Acoef = -__expf(A_log[d * D_STATE + n]);
    const float Dd    = Dv[d];
    float h = 0.0f;
    const size_t rowBase = (size_t)b * SEQ;

    auto load_chunk = [&](int l0, int buf) {
#pragma unroll
        for (int p = 0; p < 2; p++) {
            int e = p * 256 + tid, row = e >> 4, col = e & 15;
            size_t gRow = rowBase + l0 + row;
            s_dt [buf][row][col] = g_dt[gRow * D_INNER + d0 + col];
            s_u  [buf][row][col] = g_u [gRow * D_INNER + d0 + col];
            s_res[buf][row][col] = g_xr[gRow * (2 * D_INNER) + D_INNER + d0 + col];
        }
#pragma unroll
        for (int p = 0; p < 4; p++) {
            int e = p * 256 + tid, row = e >> 5, col = e & 31;
            s_bc[buf][row][col] =
                g_dbc[(rowBase + l0 + row) * DBC_COLS + DT_RANK + col];
        }
    };

    load_chunk(0, 0);
    __syncthreads();

    const int NCH = SEQ / TCH;
    for (int c = 0; c < NCH; c++) {
        const int buf = c & 1;
        if (c + 1 < NCH) load_chunk((c + 1) * TCH, buf ^ 1);

#pragma unroll 8
        for (int t = 0; t < TCH; t++) {
            float dt = s_dt[buf][t][dloc];
            float u  = s_u [buf][t][dloc];
            float Bn = s_bc[buf][t][n];
            float Cn = s_bc[buf][t][16 + n];
            float dA = __expf(dt * Acoef);
            h = fmaf(h, dA, (dt * u) * Bn);
            float v = h * Cn;
            v += __shfl_xor_sync(0xffffffffu, v, 8);
            v += __shfl_xor_sync(0xffffffffu, v, 4);
            v += __shfl_xor_sync(0xffffffffu, v, 2);
            v += __shfl_xor_sync(0xffffffffu, v, 1);
            if (n == 0) s_y[t][dloc] = fmaf(Dd, u, v);
        }
        __syncthreads();

#pragma unroll
        for (int p = 0; p < 2; p++) {
            int e = p * 256 + tid, row = e >> 4, col = e & 15;
            float r = s_res[buf][row][col];
            g_y[(rowBase + c * TCH + row) * D_INNER + d0 + col] =
                s_y[row][col] * silu_f(r);
        }
        __syncthreads();
    }
}

// ---------------- launch ----------------
extern "C" void kernel_launch(void* const* d_in, const int* in_sizes, int n_in,
                              void* d_out, int out_size)
{
    const float* x          = (const float*)d_in[0];
    const float* in_proj_w  = (const float*)d_in[1];
    const float* conv_w     = (const float*)d_in[2];
    const float* conv_b     = (const float*)d_in[3];
    const float* x_proj_w   = (const float*)d_in[4];
    const float* dt_proj_w  = (const float*)d_in[5];
    const float* dt_proj_b  = (const float*)d_in[6];
    const float* A_log      = (const float*)d_in[7];
    const float* Dv         = (const float*)d_in[8];
    const float* out_proj_w = (const float*)d_in[9];
    float* out = (float*)d_out;

    float* xr  = nullptr; cudaGetSymbolAddress((void**)&xr,  g_xr);
    float* u   = nullptr; cudaGetSymbolAddress((void**)&u,   g_u);
    float* dbc = nullptr; cudaGetSymbolAddress((void**)&dbc, g_dbc);
    float* dt  = nullptr; cudaGetSymbolAddress((void**)&dt,  g_dt);
    float* y   = nullptr; cudaGetSymbolAddress((void**)&y,   g_y);
    float* wt  = nullptr; cudaGetSymbolAddress((void**)&wt,  g_wt);

    dim3 tb(32, 8);

    // 1) in_proj: Wt = tf32(in_proj_w)^T [4096,1024]; xr = x @ W  (4096x4096, K=1024)
    transpose_cvt<<<dim3(4096 / 32, 1024 / 32), tb>>>(in_proj_w, wt, 1024, 4096);
    gemm_ldsm<<<dim3(4096 / 128, NROWS / 128), 256>>>(
        x, D_MODEL, wt, nullptr, xr, 2 * D_INNER, D_MODEL, 0);

    // 2) conv + silu
    {
        size_t total = (size_t)NROWS * D_INNER;
        conv_silu_k<<<(unsigned)((total + 255) / 256), 256>>>(conv_w, conv_b);
    }

    // 3) dbc = u @ x_proj_w  (4096x96, K=2048)
    transpose_cvt<<<dim3(96 / 32, 2048 / 32), tb>>>(x_proj_w, wt, 2048, 96);
    gemm_ldsm<<<dim3(1, NROWS / 128), 256>>>(
        u, D_INNER, wt, nullptr, dbc, DBC_COLS, D_INNER, 0);

    // 4) dt = softplus(dbc[:, :64] @ dt_proj_w + b)  (4096x2048, K=64)
    transpose_cvt<<<dim3(2048 / 32, 64 / 32), tb>>>(dt_proj_w, wt, 64, 2048);
    gemm_ldsm<<<dim3(2048 / 128, NROWS / 128), 256>>>(
        dbc, DBC_COLS, wt, dt_proj_b, dt, D_INNER, DT_RANK, 1);

    // 5) selective scan + gating -> y
    scan_k<<<dim3(D_INNER / 16, BATCH), 256>>>(A_log, Dv);

    // 6) out = y @ out_proj_w  (4096x1024, K=2048)
    transpose_cvt<<<dim3(1024 / 32, 2048 / 32), tb>>>(out_proj_w, wt, 2048, 1024);
    gemm_ldsm<<<dim3(1024 / 128, NROWS / 128), 256>>>(
        y, D_INNER, wt, nullptr, out, D_MODEL, D_INNER, 0);
}

// round 7
// speedup vs baseline: 1.4867x; 1.2620x over previous
#include <cuda_runtime.h>
#include <cuda_fp16.h>
#include <cstdint>
#include <cstddef>

// ---------------- problem constants ----------------
#define D_MODEL  1024
#define D_STATE  16
#define D_INNER  2048
#define DT_RANK  64
#define BATCH    2
#define SEQ      2048
#define NROWS    (BATCH * SEQ)           // 4096
#define DBC_COLS 96

// ---------------- scratch (static device globals; no allocation) ----------------
__device__ float  g_xr [(size_t)NROWS * (2 * D_INNER)];
__device__ float  g_u  [(size_t)NROWS * D_INNER];
__device__ float  g_dbc[(size_t)NROWS * DBC_COLS];
__device__ float  g_dt [(size_t)NROWS * D_INNER];
__device__ float  g_y  [(size_t)NROWS * D_INNER];
__device__ __half g_wt [(size_t)8 * 1024 * 1024];   // fp16 transposed weights, 4 regions

// region offsets (halves)
#define WT_IN   ((size_t)0)
#define WT_XP   ((size_t)4096 * 1024)
#define WT_DT   (WT_XP + (size_t)96 * 2048)
#define WT_OUT  (WT_DT + (size_t)2048 * 64)

// ---------------- helpers ----------------
__device__ __forceinline__ float silu_f(float x) { return x / (1.0f + __expf(-x)); }
__device__ __forceinline__ float softplus_f(float x) { return (x > 20.0f) ? x : log1pf(__expf(x)); }
__device__ __forceinline__ uint32_t smem_u32(const void* p) {
    uint32_t a;
    asm("{ .reg .u64 t; cvta.to.shared.u64 t, %1; cvt.u32.u64 %0, t; }" : "=r"(a) : "l"(p));
    return a;
}
__device__ __forceinline__ void mma_f16(float* d, const uint32_t* a, const uint32_t* b) {
    asm volatile(
        "mma.sync.aligned.m16n8k16.row.col.f32.f16.f16.f32 "
        "{%0,%1,%2,%3}, {%4,%5,%6,%7}, {%8,%9}, {%0,%1,%2,%3};"
        : "+f"(d[0]), "+f"(d[1]), "+f"(d[2]), "+f"(d[3])
        : "r"(a[0]), "r"(a[1]), "r"(a[2]), "r"(a[3]), "r"(b[0]), "r"(b[1]));
}
__device__ __forceinline__ void ldsm4(uint32_t& r0, uint32_t& r1, uint32_t& r2, uint32_t& r3,
                                      uint32_t addr) {
    asm volatile("ldmatrix.sync.aligned.m8n8.x4.shared.b16 {%0,%1,%2,%3}, [%4];"
                 : "=r"(r0), "=r"(r1), "=r"(r2), "=r"(r3) : "r"(addr));
}
__device__ __forceinline__ uint32_t pack_h2(float a, float b) {
    __half2 h = __float22half2_rn(make_float2(a, b));
    return *reinterpret_cast<uint32_t*>(&h);
}

// ---------------- fp16 tensor-core GEMM (ldmatrix feed, m16n8k16) ----------------
// C[M, N_total] = A[M, K] (row-major fp32, lda) @ Wt[N, K]^T (row-major fp16)
// Block 128x128, BK=32, 8 warps (2 M x 4 N), warp tile 64x32.
// Smem row stride 40 halves (80 B) -> ldmatrix conflict-free.
// mode 0: plain store; mode 1: softplus(acc + bias[col]).
#define BKH 32
#define RSH 40
__global__ __launch_bounds__(256, 2) void gemm_h(
    const float* __restrict__ A, int lda,
    const __half* __restrict__ Wt,
    const float* __restrict__ bias,
    float* __restrict__ C, int N_total, int K, int mode)
{
    __shared__ __half As[2][128][RSH];   // 20 KB
    __shared__ __half Bs[2][128][RSH];   // 20 KB

    const int tid  = threadIdx.x;
    const int w    = tid >> 5;
    const int l    = tid & 31;
    const int mBase = blockIdx.y * 128;
    const int nBase = blockIdx.x * 128;
    const int wmB  = (w & 1) * 64;     // warp m origin
    const int wnB  = (w >> 1) * 32;    // warp n origin

    // loader map: thread -> row tid>>1, 16-half chunk (tid&1)
    const int ldRow = tid >> 1;
    const int ldC   = (tid & 1) * 16;  // halves (== elements)

    // ldmatrix lane address components (rows; col-halves)
    const int aRowOff = (l & 7) + ((l >> 3) & 1) * 8;
    const int aColH   = ((l >> 4) & 1) * 8;
    const int bRowOff = (l & 7) + ((l >> 4) & 1) * 8;
    const int bColH   = ((l >> 3) & 1) * 8;

    const uint32_t sAs = smem_u32(&As[0][0][0]);
    const uint32_t sBs = smem_u32(&Bs[0][0][0]);

    float acc[4][4][4];
#pragma unroll
    for (int i = 0; i < 4; i++)
#pragma unroll
        for (int j = 0; j < 4; j++)
#pragma unroll
            for (int q = 0; q < 4; q++) acc[i][j][q] = 0.0f;

    uint4 rah[2], rbh[2];   // staged halves: A 16, B 16

    auto ldg = [&](int k0) {
        const float* ap = A + (size_t)(mBase + ldRow) * lda + k0 + ldC;
        float4 f0 = *reinterpret_cast<const float4*>(ap);
        float4 f1 = *reinterpret_cast<const float4*>(ap + 4);
        float4 f2 = *reinterpret_cast<const float4*>(ap + 8);
        float4 f3 = *reinterpret_cast<const float4*>(ap + 12);
        rah[0].x = pack_h2(f0.x, f0.y); rah[0].y = pack_h2(f0.z, f0.w);
        rah[0].z = pack_h2(f1.x, f1.y); rah[0].w = pack_h2(f1.z, f1.w);
        rah[1].x = pack_h2(f2.x, f2.y); rah[1].y = pack_h2(f2.z, f2.w);
        rah[1].z = pack_h2(f3.x, f3.y); rah[1].w = pack_h2(f3.z, f3.w);
        int n = nBase + ldRow;
        if (n < N_total) {
            const __half* bp = Wt + (size_t)n * K + k0 + ldC;
            rbh[0] = *reinterpret_cast<const uint4*>(bp);
            rbh[1] = *reinterpret_cast<const uint4*>(bp + 8);
        } else {
            rbh[0] = make_uint4(0, 0, 0, 0);
            rbh[1] = rbh[0];
        }
    };
    auto sts = [&](int buf) {
        *reinterpret_cast<uint4*>(&As[buf][ldRow][ldC])     = rah[0];
        *reinterpret_cast<uint4*>(&As[buf][ldRow][ldC + 8]) = rah[1];
        *reinterpret_cast<uint4*>(&Bs[buf][ldRow][ldC])     = rbh[0];
        *reinterpret_cast<uint4*>(&Bs[buf][ldRow][ldC + 8]) = rbh[1];
    };

    auto compute = [&](int buf) {
        const uint32_t aB = sAs + (uint32_t)(((buf * 128 + wmB + aRowOff) * RSH + aColH) * 2);
        const uint32_t bB = sBs + (uint32_t)(((buf * 128 + wnB + bRowOff) * RSH + bColH) * 2);
#pragma unroll
        for (int s = 0; s < 2; s++) {
            uint32_t af[4][4], bf[4][2];
#pragma unroll
            for (int i = 0; i < 4; i++)
                ldsm4(af[i][0], af[i][1], af[i][2], af[i][3],
                      aB + (uint32_t)((i * 16 * RSH + s * 16) * 2));
#pragma unroll
            for (int jj = 0; jj < 2; jj++)
                ldsm4(bf[2 * jj][0], bf[2 * jj][1], bf[2 * jj + 1][0], bf[2 * jj + 1][1],
                      bB + (uint32_t)((jj * 16 * RSH + s * 16) * 2));
#pragma unroll
            for (int i = 0; i < 4; i++)
#pragma unroll
                for (int j = 0; j < 4; j++)
                    mma_f16(acc[i][j], af[i], bf[j]);
        }
    };

    // prologue
    ldg(0); sts(0);
    __syncthreads();

    const int nt = K / BKH;
    for (int t = 0; t < nt; t++) {
        const int buf = t & 1;
        const bool more = (t + 1 < nt);
        if (more) ldg((t + 1) * BKH);
        compute(buf);
        if (more) sts(buf ^ 1);
        __syncthreads();
    }

    // epilogue
#pragma unroll
    for (int i = 0; i < 4; i++) {
        int r0 = mBase + wmB + i * 16 + (l >> 2);
#pragma unroll
        for (int j = 0; j < 4; j++) {
            int cc = nBase + wnB + j * 8 + (l & 3) * 2;
            if (cc < N_total) {
                float2 v0, v1;
                v0.x = acc[i][j][0]; v0.y = acc[i][j][1];
                v1.x = acc[i][j][2]; v1.y = acc[i][j][3];
                if (mode == 1) {
                    float b0 = bias[cc], b1 = bias[cc + 1];
                    v0.x = softplus_f(v0.x + b0); v0.y = softplus_f(v0.y + b1);
                    v1.x = softplus_f(v1.x + b0); v1.y = softplus_f(v1.y + b1);
                }
                *reinterpret_cast<float2*>(C + (size_t)r0 * N_total + cc)       = v0;
                *reinterpret_cast<float2*>(C + (size_t)(r0 + 8) * N_total + cc) = v1;
            }
        }
    }
}

// ---------------- weight transpose to fp16: out[n][k] = fp16(in[k][n]) ----------------
__global__ void transpose_h(const float* __restrict__ in, __half* __restrict__ out, int K, int N)
{
    __shared__ float t[32][33];
    const int n0 = blockIdx.x * 32, k0 = blockIdx.y * 32;
    for (int r = threadIdx.y; r < 32; r += 8)
        t[r][threadIdx.x] = in[(size_t)(k0 + r) * N + n0 + threadIdx.x];
    __syncthreads();
    for (int r = threadIdx.y; r < 32; r += 8)
        out[(size_t)(n0 + r) * K + k0 + threadIdx.x] = __float2half_rn(t[threadIdx.x][r]);
}

// ---------------- causal depthwise conv1d + silu ----------------
__global__ void conv_silu_k(const float* __restrict__ conv_w,
                            const float* __restrict__ conv_b)
{
    size_t idx = (size_t)blockIdx.x * blockDim.x + threadIdx.x;
    if (idx >= (size_t)NROWS * D_INNER) return;
    int d = (int)(idx % D_INNER);
    int l = (int)((idx / D_INNER) % SEQ);
    int b = (int)(idx / ((size_t)D_INNER * SEQ));

    float acc = conv_b[d];
    const float w0 = conv_w[d * 4 + 0];
    const float w1 = conv_w[d * 4 + 1];
    const float w2 = conv_w[d * 4 + 2];
    const float w3 = conv_w[d * 4 + 3];
    const size_t base = ((size_t)b * SEQ) * (2 * D_INNER) + d;
    const size_t rs = 2 * D_INNER;
    if (l - 3 >= 0) acc = fmaf(g_xr[base + (size_t)(l - 3) * rs], w0, acc);
    if (l - 2 >= 0) acc = fmaf(g_xr[base + (size_t)(l - 2) * rs], w1, acc);
    if (l - 1 >= 0) acc = fmaf(g_xr[base + (size_t)(l - 1) * rs], w2, acc);
    acc = fmaf(g_xr[base + (size_t)l * rs], w3, acc);

    g_u[((size_t)b * SEQ + l) * D_INNER + d] = silu_f(acc);
}

// ---------------- selective scan (smem-chunked, double-buffered) ----------------
#define TCH 32
__global__ __launch_bounds__(256) void scan_k(
    const float* __restrict__ A_log,
    const float* __restrict__ Dv)
{
    __shared__ float s_dt [2][TCH][16];
    __shared__ float s_u  [2][TCH][16];
    __shared__ float s_res[2][TCH][16];
    __shared__ float s_bc [2][TCH][32];
    __shared__ float s_y  [TCH][16];

    const int b    = blockIdx.y;
    const int d0   = blockIdx.x * 16;
    const int tid  = threadIdx.x;
    const int dloc = tid >> 4;
    const int n    = tid & 15;
    const int d    = d0 + dloc;

    const float Acoef = -__expf(A_log[d * D_STATE + n]);
    const float Dd    = Dv[d];
    float h = 0.0f;
    const size_t rowBase = (size_t)b * SEQ;

    auto load_chunk = [&](int l0, int buf) {
#pragma unroll
        for (int p = 0; p < 2; p++) {
            int e = p * 256 + tid, row = e >> 4, col = e & 15;
            size_t gRow = rowBase + l0 + row;
            s_dt [buf][row][col] = g_dt[gRow * D_INNER + d0 + col];
            s_u  [buf][row][col] = g_u [gRow * D_INNER + d0 + col];
            s_res[buf][row][col] = g_xr[gRow * (2 * D_INNER) + D_INNER + d0 + col];
        }
#pragma unroll
        for (int p = 0; p < 4; p++) {
            int e = p * 256 + tid, row = e >> 5, col = e & 31;
            s_bc[buf][row][col] =
                g_dbc[(rowBase + l0 + row) * DBC_COLS + DT_RANK + col];
        }
    };

    load_chunk(0, 0);
    __syncthreads();

    const int NCH = SEQ / TCH;
    for (int c = 0; c < NCH; c++) {
        const int buf = c & 1;
        if (c + 1 < NCH) load_chunk((c + 1) * TCH, buf ^ 1);

#pragma unroll 8
        for (int t = 0; t < TCH; t++) {
            float dt = s_dt[buf][t][dloc];
            float u  = s_u [buf][t][dloc];
            float Bn = s_bc[buf][t][n];
            float Cn = s_bc[buf][t][16 + n];
            float dA = __expf(dt * Acoef);
            h = fmaf(h, dA, (dt * u) * Bn);
            float v = h * Cn;
            v += __shfl_xor_sync(0xffffffffu, v, 8);
            v += __shfl_xor_sync(0xffffffffu, v, 4);
            v += __shfl_xor_sync(0xffffffffu, v, 2);
            v += __shfl_xor_sync(0xffffffffu, v, 1);
            if (n == 0) s_y[t][dloc] = fmaf(Dd, u, v);
        }
        __syncthreads();

#pragma unroll
        for (int p = 0; p < 2; p++) {
            int e = p * 256 + tid, row = e >> 4, col = e & 15;
            float r = s_res[buf][row][col];
            g_y[(rowBase + c * TCH + row) * D_INNER + d0 + col] =
                s_y[row][col] * silu_f(r);
        }
        __syncthreads();
    }
}

// ---------------- launch ----------------
extern "C" void kernel_launch(void* const* d_in, const int* in_sizes, int n_in,
                              void* d_out, int out_size)
{
    const float* x          = (const float*)d_in[0];
    const float* in_proj_w  = (const float*)d_in[1];
    const float* conv_w     = (const float*)d_in[2];
    const float* conv_b     = (const float*)d_in[3];
    const float* x_proj_w   = (const float*)d_in[4];
    const float* dt_proj_w  = (const float*)d_in[5];
    const float* dt_proj_b  = (const float*)d_in[6];
    const float* A_log      = (const float*)d_in[7];
    const float* Dv         = (const float*)d_in[8];
    const float* out_proj_w = (const float*)d_in[9];
    float* out = (float*)d_out;

    float*  xr  = nullptr; cudaGetSymbolAddress((void**)&xr,  g_xr);
    float*  u   = nullptr; cudaGetSymbolAddress((void**)&u,   g_u);
    float*  dbc = nullptr; cudaGetSymbolAddress((void**)&dbc, g_dbc);
    float*  dt  = nullptr; cudaGetSymbolAddress((void**)&dt,  g_dt);
    float*  y   = nullptr; cudaGetSymbolAddress((void**)&y,   g_y);
    __half* wt  = nullptr; cudaGetSymbolAddress((void**)&wt,  g_wt);

    dim3 tb(32, 8);

    // launches 0-4: all weight transposes up front (disjoint regions)
    transpose_h<<<dim3(96 / 32, 2048 / 32), tb>>>(x_proj_w,  wt + WT_XP, 2048, 96);
    transpose_h<<<dim3(2048 / 32, 64 / 32), tb>>>(dt_proj_w, wt + WT_DT, 64, 2048);
    transpose_h<<<dim3(1024 / 32, 2048 / 32), tb>>>(out_proj_w, wt + WT_OUT, 2048, 1024);
    transpose_h<<<dim3(2048 / 32, 1024 / 32), tb>>>(in_proj_w, wt + WT_IN, 1024, 4096);
    transpose_h<<<dim3(2048 / 32, 1024 / 32), tb>>>(in_proj_w + 2048,
                                                    wt + WT_IN + (size_t)2048 * 1024, 1024, 4096);

    // launch 5 (ncu -s 5 -c 1 captures this): in_proj GEMM (4096x4096, K=1024)
    gemm_h<<<dim3(4096 / 128, NROWS / 128), 256>>>(
        x, D_MODEL, wt + WT_IN, nullptr, xr, 2 * D_INNER, D_MODEL, 0);

    // conv + silu
    {
        size_t total = (size_t)NROWS * D_INNER;
        conv_silu_k<<<(unsigned)((total + 255) / 256), 256>>>(conv_w, conv_b);
    }

    // dbc = u @ x_proj_w  (4096x96, K=2048)
    gemm_h<<<dim3(1, NROWS / 128), 256>>>(
        u, D_INNER, wt + WT_XP, nullptr, dbc, DBC_COLS, D_INNER, 0);

    // dt = softplus(dbc[:, :64] @ dt_proj_w + b)  (4096x2048, K=64)
    gemm_h<<<dim3(2048 / 128, NROWS / 128), 256>>>(
        dbc, DBC_COLS, wt + WT_DT, dt_proj_b, dt, D_INNER, DT_RANK, 1);

    // selective scan + gating -> y
    scan_k<<<dim3(D_INNER / 16, BATCH), 256>>>(A_log, Dv);

    // out = y @ out_proj_w  (4096x1024, K=2048)
    gemm_h<<<dim3(1024 / 128, NROWS / 128), 256>>>(
        y, D_INNER, wt + WT_OUT, nullptr, out, D_MODEL, D_INNER, 0);
}

// round 8
// speedup vs baseline: 1.6625x; 1.1182x over previous
#include <cuda_runtime.h>
#include <cuda_fp16.h>
#include <cstdint>
#include <cstddef>

// ---------------- problem constants ----------------
#define D_MODEL  1024
#define D_STATE  16
#define D_INNER  2048
#define DT_RANK  64
#define BATCH    2
#define SEQ      2048
#define NROWS    (BATCH * SEQ)           // 4096
#define DBC_COLS 96
#define SPLITK   8

// ---------------- scratch (static device globals; no allocation) ----------------
__device__ float  g_xr [(size_t)NROWS * (2 * D_INNER)];
__device__ float  g_u  [(size_t)NROWS * D_INNER];
__device__ float  g_dbc[(size_t)NROWS * DBC_COLS];
__device__ float  g_dt [(size_t)NROWS * D_INNER];
__device__ float  g_y  [(size_t)NROWS * D_INNER];
__device__ float  g_sp [(size_t)SPLITK * NROWS * DBC_COLS];  // split-K partials (12.6MB)
__device__ __half g_wt [(size_t)8 * 1024 * 1024];            // fp16 transposed weights

// region offsets (halves)
#define WT_IN   ((size_t)0)
#define WT_XP   ((size_t)4096 * 1024)
#define WT_DT   (WT_XP + (size_t)96 * 2048)
#define WT_OUT  (WT_DT + (size_t)2048 * 64)

// ---------------- helpers ----------------
__device__ __forceinline__ float silu_f(float x) { return x / (1.0f + __expf(-x)); }
__device__ __forceinline__ float softplus_f(float x) { return (x > 20.0f) ? x : log1pf(__expf(x)); }
__device__ __forceinline__ uint32_t smem_u32(const void* p) {
    uint32_t a;
    asm("{ .reg .u64 t; cvta.to.shared.u64 t, %1; cvt.u32.u64 %0, t; }" : "=r"(a) : "l"(p));
    return a;
}
__device__ __forceinline__ void mma_f16(float* d, const uint32_t* a, const uint32_t* b) {
    asm volatile(
        "mma.sync.aligned.m16n8k16.row.col.f32.f16.f16.f32 "
        "{%0,%1,%2,%3}, {%4,%5,%6,%7}, {%8,%9}, {%0,%1,%2,%3};"
        : "+f"(d[0]), "+f"(d[1]), "+f"(d[2]), "+f"(d[3])
        : "r"(a[0]), "r"(a[1]), "r"(a[2]), "r"(a[3]), "r"(b[0]), "r"(b[1]));
}
__device__ __forceinline__ void ldsm4(uint32_t& r0, uint32_t& r1, uint32_t& r2, uint32_t& r3,
                                      uint32_t addr) {
    asm volatile("ldmatrix.sync.aligned.m8n8.x4.shared.b16 {%0,%1,%2,%3}, [%4];"
                 : "=r"(r0), "=r"(r1), "=r"(r2), "=r"(r3) : "r"(addr));
}
__device__ __forceinline__ uint32_t pack_h2(float a, float b) {
    __half2 h = __float22half2_rn(make_float2(a, b));
    return *reinterpret_cast<uint32_t*>(&h);
}

// ---------------- fp16 tensor-core GEMM (ldmatrix feed, m16n8k16, optional split-K) ----------------
// C(+z*Cstride)[M, N_total] += A[M, z*K_sub ...][lda] @ Wt[N, z*K_sub ...][ldw]^T
// Block 128x128, BK=32, 8 warps (2M x 4N), warp tile 64x32.
// mode 0: plain store; mode 1: softplus(acc + bias[col]).
#define BKH 32
#define RSH 40
__global__ __launch_bounds__(256, 2) void gemm_h(
    const float* __restrict__ A, int lda,
    const __half* __restrict__ Wt, int ldw,
    const float* __restrict__ bias,
    float* __restrict__ C, int N_total, int K_sub, int mode, size_t Cstride)
{
    __shared__ __half As[2][128][RSH];   // 20 KB
    __shared__ __half Bs[2][128][RSH];   // 20 KB

    const int tid  = threadIdx.x;
    const int w    = tid >> 5;
    const int l    = tid & 31;
    const int mBase = blockIdx.y * 128;
    const int nBase = blockIdx.x * 128;
    const int kOff  = blockIdx.z * K_sub;
    C += (size_t)blockIdx.z * Cstride;

    const int wmB  = (w & 1) * 64;
    const int wnB  = (w >> 1) * 32;

    const int ldRow = tid >> 1;
    const int ldC   = (tid & 1) * 16;

    const int aRowOff = (l & 7) + ((l >> 3) & 1) * 8;
    const int aColH   = ((l >> 4) & 1) * 8;
    const int bRowOff = (l & 7) + ((l >> 4) & 1) * 8;
    const int bColH   = ((l >> 3) & 1) * 8;

    const uint32_t sAs = smem_u32(&As[0][0][0]);
    const uint32_t sBs = smem_u32(&Bs[0][0][0]);

    float acc[4][4][4];
#pragma unroll
    for (int i = 0; i < 4; i++)
#pragma unroll
        for (int j = 0; j < 4; j++)
#pragma unroll
            for (int q = 0; q < 4; q++) acc[i][j][q] = 0.0f;

    uint4 rah[2], rbh[2];

    auto ldg = [&](int k0) {
        const float* ap = A + (size_t)(mBase + ldRow) * lda + kOff + k0 + ldC;
        float4 f0 = *reinterpret_cast<const float4*>(ap);
        float4 f1 = *reinterpret_cast<const float4*>(ap + 4);
        float4 f2 = *reinterpret_cast<const float4*>(ap + 8);
        float4 f3 = *reinterpret_cast<const float4*>(ap + 12);
        rah[0].x = pack_h2(f0.x, f0.y); rah[0].y = pack_h2(f0.z, f0.w);
        rah[0].z = pack_h2(f1.x, f1.y); rah[0].w = pack_h2(f1.z, f1.w);
        rah[1].x = pack_h2(f2.x, f2.y); rah[1].y = pack_h2(f2.z, f2.w);
        rah[1].z = pack_h2(f3.x, f3.y); rah[1].w = pack_h2(f3.z, f3.w);
        int n = nBase + ldRow;
        if (n < N_total) {
            const __half* bp = Wt + (size_t)n * ldw + kOff + k0 + ldC;
            rbh[0] = *reinterpret_cast<const uint4*>(bp);
            rbh[1] = *reinterpret_cast<const uint4*>(bp + 8);
        } else {
            rbh[0] = make_uint4(0, 0, 0, 0);
            rbh[1] = rbh[0];
        }
    };
    auto sts = [&](int buf) {
        *reinterpret_cast<uint4*>(&As[buf][ldRow][ldC])     = rah[0];
        *reinterpret_cast<uint4*>(&As[buf][ldRow][ldC + 8]) = rah[1];
        *reinterpret_cast<uint4*>(&Bs[buf][ldRow][ldC])     = rbh[0];
        *reinterpret_cast<uint4*>(&Bs[buf][ldRow][ldC + 8]) = rbh[1];
    };
    auto compute = [&](int buf) {
        const uint32_t aB = sAs + (uint32_t)(((buf * 128 + wmB + aRowOff) * RSH + aColH) * 2);
        const uint32_t bB = sBs + (uint32_t)(((buf * 128 + wnB + bRowOff) * RSH + bColH) * 2);
#pragma unroll
        for (int s = 0; s < 2; s++) {
            uint32_t af[4][4], bf[4][2];
#pragma unroll
            for (int i = 0; i < 4; i++)
                ldsm4(af[i][0], af[i][1], af[i][2], af[i][3],
                      aB + (uint32_t)((i * 16 * RSH + s * 16) * 2));
#pragma unroll
            for (int jj = 0; jj < 2; jj++)
                ldsm4(bf[2 * jj][0], bf[2 * jj][1], bf[2 * jj + 1][0], bf[2 * jj + 1][1],
                      bB + (uint32_t)((jj * 16 * RSH + s * 16) * 2));
#pragma unroll
            for (int i = 0; i < 4; i++)
#pragma unroll
                for (int j = 0; j < 4; j++)
                    mma_f16(acc[i][j], af[i], bf[j]);
        }
    };

    ldg(0); sts(0);
    __syncthreads();

    const int nt = K_sub / BKH;
    for (int t = 0; t < nt; t++) {
        const int buf = t & 1;
        const bool more = (t + 1 < nt);
        if (more) ldg((t + 1) * BKH);
        compute(buf);
        if (more) sts(buf ^ 1);
        __syncthreads();
    }

#pragma unroll
    for (int i = 0; i < 4; i++) {
        int r0 = mBase + wmB + i * 16 + (l >> 2);
#pragma unroll
        for (int j = 0; j < 4; j++) {
            int cc = nBase + wnB + j * 8 + (l & 3) * 2;
            if (cc < N_total) {
                float2 v0, v1;
                v0.x = acc[i][j][0]; v0.y = acc[i][j][1];
                v1.x = acc[i][j][2]; v1.y = acc[i][j][3];
                if (mode == 1) {
                    float b0 = bias[cc], b1 = bias[cc + 1];
                    v0.x = softplus_f(v0.x + b0); v0.y = softplus_f(v0.y + b1);
                    v1.x = softplus_f(v1.x + b0); v1.y = softplus_f(v1.y + b1);
                }
                *reinterpret_cast<float2*>(C + (size_t)r0 * N_total + cc)       = v0;
                *reinterpret_cast<float2*>(C + (size_t)(r0 + 8) * N_total + cc) = v1;
            }
        }
    }
}

// ---------------- split-K reduction: dbc = sum_z g_sp[z] ----------------
__global__ void reduce_split_k(float* __restrict__ dbc)
{
    int i = blockIdx.x * 256 + threadIdx.x;
    if (i >= NROWS * DBC_COLS) return;
    float s = 0.0f;
#pragma unroll
    for (int z = 0; z < SPLITK; z++)
        s += g_sp[(size_t)z * NROWS * DBC_COLS + i];
    dbc[i] = s;
}

// ---------------- weight transpose to fp16: out[n][k] = fp16(in[k][n]) ----------------
__global__ void transpose_h(const float* __restrict__ in, __half* __restrict__ out, int K, int N)
{
    __shared__ float t[32][33];
    const int n0 = blockIdx.x * 32, k0 = blockIdx.y * 32;
    for (int r = threadIdx.y; r < 32; r += 8)
        t[r][threadIdx.x] = in[(size_t)(k0 + r) * N + n0 + threadIdx.x];
    __syncthreads();
    for (int r = threadIdx.y; r < 32; r += 8)
        out[(size_t)(n0 + r) * K + k0 + threadIdx.x] = __float2half_rn(t[threadIdx.x][r]);
}

// ---------------- causal depthwise conv1d + silu (float4 over d) ----------------
__global__ void conv_silu4(const float* __restrict__ conv_w,
                           const float* __restrict__ conv_b)
{
    int idx = blockIdx.x * 256 + threadIdx.x;     // NROWS * 512 total
    if (idx >= NROWS * (D_INNER / 4)) return;
    int d4  = idx & (D_INNER / 4 - 1);
    int row = idx >> 9;                            // global token row
    int l   = row & (SEQ - 1);
    int b   = row >> 11;
    int d   = d4 * 4;

    const float4* cw4 = reinterpret_cast<const float4*>(conv_w);
    float4 wa = cw4[d + 0];   // taps of channel d
    float4 wb = cw4[d + 1];
    float4 wc = cw4[d + 2];
    float4 wd = cw4[d + 3];
    float4 acc = *reinterpret_cast<const float4*>(conv_b + d);

    const size_t base = ((size_t)b * SEQ) * (2 * D_INNER) + d;
    float4 xv[4];
#pragma unroll
    for (int k = 0; k < 4; k++) {
        int ll = l - 3 + k;
        xv[k] = (ll >= 0) ? *reinterpret_cast<const float4*>(&g_xr[base + (size_t)ll * (2 * D_INNER)])
                          : make_float4(0.f, 0.f, 0.f, 0.f);
    }
    acc.x += xv[0].x * wa.x + xv[1].x * wa.y + xv[2].x * wa.z + xv[3].x * wa.w;
    acc.y += xv[0].y * wb.x + xv[1].y * wb.y + xv[2].y * wb.z + xv[3].y * wb.w;
    acc.z += xv[0].z * wc.x + xv[1].z * wc.y + xv[2].z * wc.z + xv[3].z * wc.w;
    acc.w += xv[0].w * wd.x + xv[1].w * wd.y + xv[2].w * wd.z + xv[3].w * wd.w;

    float4 o;
    o.x = silu_f(acc.x); o.y = silu_f(acc.y); o.z = silu_f(acc.z); o.w = silu_f(acc.w);
    *reinterpret_cast<float4*>(&g_u[(size_t)row * D_INNER + d]) = o;
}

// ---------------- selective scan (smem-chunked, double-buffered) ----------------
#define TCH 32
__global__ __launch_bounds__(256) void scan_k(
    const float* __restrict__ A_log,
    const float* __restrict__ Dv)
{
    __shared__ float s_dt [2][TCH][16];
    __shared__ float s_u  [2][TCH][16];
    __shared__ float s_res[2][TCH][16];
    __shared__ float s_bc [2][TCH][32];
    __shared__ float s_y  [TCH][16];

    const int b    = blockIdx.y;
    const int d0   = blockIdx.x * 16;
    const int tid  = threadIdx.x;
    const int dloc = tid >> 4;
    const int n    = tid & 15;
    const int d    = d0 + dloc;

    const float Acoef = -__expf(A_log[d * D_STATE + n]);
    const float Dd    = Dv[d];
    float h = 0.0f;
    const size_t rowBase = (size_t)b * SEQ;

    auto load_chunk = [&](int l0, int buf) {
#pragma unroll
        for (int p = 0; p < 2; p++) {
            int e = p * 256 + tid, row = e >> 4, col = e & 15;
            size_t gRow = rowBase + l0 + row;
            s_dt [buf][row][col] = g_dt[gRow * D_INNER + d0 + col];
            s_u  [buf][row][col] = g_u [gRow * D_INNER + d0 + col];
            s_res[buf][row][col] = g_xr[gRow * (2 * D_INNER) + D_INNER + d0 + col];
        }
#pragma unroll
        for (int p = 0; p < 4; p++) {
            int e = p * 256 + tid, row = e >> 5, col = e & 31;
            s_bc[buf][row][col] =
                g_dbc[(rowBase + l0 + row) * DBC_COLS + DT_RANK + col];
        }
    };

    load_chunk(0, 0);
    __syncthreads();

    const int NCH = SEQ / TCH;
    for (int c = 0; c < NCH; c++) {
        const int buf = c & 1;
        if (c + 1 < NCH) load_chunk((c + 1) * TCH, buf ^ 1);

#pragma unroll 8
        for (int t = 0; t < TCH; t++) {
            float dt = s_dt[buf][t][dloc];
            float u  = s_u [buf][t][dloc];
            float Bn = s_bc[buf][t][n];
            float Cn = s_bc[buf][t][16 + n];
            float dA = __expf(dt * Acoef);
            h = fmaf(h, dA, (dt * u) * Bn);
            float v = h * Cn;
            v += __shfl_xor_sync(0xffffffffu, v, 8);
            v += __shfl_xor_sync(0xffffffffu, v, 4);
            v += __shfl_xor_sync(0xffffffffu, v, 2);
            v += __shfl_xor_sync(0xffffffffu, v, 1);
            if (n == 0) s_y[t][dloc] = fmaf(Dd, u, v);
        }
        __syncthreads();

#pragma unroll
        for (int p = 0; p < 2; p++) {
            int e = p * 256 + tid, row = e >> 4, col = e & 15;
            float r = s_res[buf][row][col];
            g_y[(rowBase + c * TCH + row) * D_INNER + d0 + col] =
                s_y[row][col] * silu_f(r);
        }
        __syncthreads();
    }
}

// ---------------- launch ----------------
extern "C" void kernel_launch(void* const* d_in, const int* in_sizes, int n_in,
                              void* d_out, int out_size)
{
    const float* x          = (const float*)d_in[0];
    const float* in_proj_w  = (const float*)d_in[1];
    const float* conv_w     = (const float*)d_in[2];
    const float* conv_b     = (const float*)d_in[3];
    const float* x_proj_w   = (const float*)d_in[4];
    const float* dt_proj_w  = (const float*)d_in[5];
    const float* dt_proj_b  = (const float*)d_in[6];
    const float* A_log      = (const float*)d_in[7];
    const float* Dv         = (const float*)d_in[8];
    const float* out_proj_w = (const float*)d_in[9];
    float* out = (float*)d_out;

    float*  xr  = nullptr; cudaGetSymbolAddress((void**)&xr,  g_xr);
    float*  u   = nullptr; cudaGetSymbolAddress((void**)&u,   g_u);
    float*  dbc = nullptr; cudaGetSymbolAddress((void**)&dbc, g_dbc);
    float*  dt  = nullptr; cudaGetSymbolAddress((void**)&dt,  g_dt);
    float*  y   = nullptr; cudaGetSymbolAddress((void**)&y,   g_y);
    float*  sp  = nullptr; cudaGetSymbolAddress((void**)&sp,  g_sp);
    __half* wt  = nullptr; cudaGetSymbolAddress((void**)&wt,  g_wt);

    dim3 tb(32, 8);

    // idx 0-2: transposes
    transpose_h<<<dim3(3, 64), tb>>>(x_proj_w,  wt + WT_XP, 2048, 96);
    transpose_h<<<dim3(64, 2), tb>>>(dt_proj_w, wt + WT_DT, 64, 2048);
    transpose_h<<<dim3(128, 32), tb>>>(in_proj_w, wt + WT_IN, 1024, 4096);

    // idx 3 (ncu-captured): in_proj GEMM  (4096 x 4096, K=1024)
    gemm_h<<<dim3(32, 32), 256>>>(
        x, D_MODEL, wt + WT_IN, D_MODEL, nullptr, xr, 2 * D_INNER, D_MODEL, 0, 0);

    // idx 4: out_proj transpose
    transpose_h<<<dim3(32, 64), tb>>>(out_proj_w, wt + WT_OUT, 2048, 1024);

    // idx 5: conv + silu (float4)
    conv_silu4<<<(NROWS * (D_INNER / 4) + 255) / 256, 256>>>(conv_w, conv_b);

    // idx 6-7: dbc = u @ x_proj_w  (4096x96, K=2048) via split-K x8
    gemm_h<<<dim3(1, 32, SPLITK), 256>>>(
        u, D_INNER, wt + WT_XP, D_INNER, nullptr, sp, DBC_COLS, D_INNER / SPLITK, 0,
        (size_t)NROWS * DBC_COLS);
    reduce_split_k<<<(NROWS * DBC_COLS + 255) / 256, 256>>>(dbc);

    // idx 8: dt = softplus(dbc[:, :64] @ dt_proj_w + b)  (4096x2048, K=64)
    gemm_h<<<dim3(16, 32), 256>>>(
        dbc, DBC_COLS, wt + WT_DT, DT_RANK, dt_proj_b, dt, D_INNER, DT_RANK, 1, 0);

    // idx 9: selective scan + gating -> y
    scan_k<<<dim3(D_INNER / 16, BATCH), 256>>>(A_log, Dv);

    // idx 10: out = y @ out_proj_w  (4096x1024, K=2048)
    gemm_h<<<dim3(8, 32), 256>>>(
        y, D_INNER, wt + WT_OUT, D_INNER, nullptr, out, D_MODEL, D_INNER, 0, 0);
}